// round 12
// baseline (speedup 1.0000x reference)
#include <cuda_runtime.h>
#include <cuda_fp16.h>
#include <math.h>
#include <stdint.h>

#define KDIM 128
#define HDIM 32
#define TM   128
#define NT   512
#define LD2  68      // row stride in 32-bit words (=136 halves); 68 % 32 == 4 -> conflict-free

// ---------- helpers ----------
__device__ __forceinline__ uint32_t pack_h2(float a, float b) {
    __half2 h = __floats2half2_rn(a, b);
    return *reinterpret_cast<uint32_t*>(&h);
}
// D += A(16x16,row) * B(16x8,col)   fp16 -> f32
__device__ __forceinline__ void mma16(float& d0, float& d1, float& d2, float& d3,
                                      uint32_t a0, uint32_t a1, uint32_t a2, uint32_t a3,
                                      uint32_t b0, uint32_t b1) {
    asm("mma.sync.aligned.m16n8k16.row.col.f32.f16.f16.f32 "
        "{%0,%1,%2,%3}, {%4,%5,%6,%7}, {%8,%9}, {%0,%1,%2,%3};"
        : "+f"(d0), "+f"(d1), "+f"(d2), "+f"(d3)
        : "r"(a0), "r"(a1), "r"(a2), "r"(a3), "r"(b0), "r"(b1));
}
__device__ __forceinline__ float gelu_exact(float x) {
    return 0.5f * x * (1.0f + erff(x * 0.7071067811865476f));
}

// ---- smem word(32-bit) offsets ----
#define G_OFF   0u                        // 128*LD2 words (G, reused as h)
#define W1_OFF  (128u * LD2)              // 8704
#define W2_OFF  (W1_OFF + 128u * LD2)     // 17408
#define AUX_OFF (W2_OFF + 32u * LD2)      // 19584
// aux: s[128], mus[128], ivs[128], cs[128], b1s[128], b2s[32] = 672 floats
#define SMEM_BYTES ((AUX_OFF + 672u) * 4u)   // 81024 B -> 2 CTAs/SM

extern __shared__ float smem_f[];

__global__ __launch_bounds__(NT, 2)
void spatial_encoder_h16(
    const float* __restrict__ coord, const int* __restrict__ node_type,
    const float* __restrict__ gmeans, const float* __restrict__ gstds,
    const float* __restrict__ mul_w, const float* __restrict__ bias_w,
    const float* __restrict__ W1, const float* __restrict__ b1,
    const float* __restrict__ W2, const float* __restrict__ b2,
    float* __restrict__ out, int n, long long nn, long long Ptotal)
{
    uint32_t* Gs  = (uint32_t*)(smem_f + G_OFF);
    uint32_t* W1s = (uint32_t*)(smem_f + W1_OFF);
    uint32_t* W2s = (uint32_t*)(smem_f + W2_OFF);
    float* s_sm = smem_f + AUX_OFF;
    float* mus  = s_sm + 128;
    float* ivs  = mus + 128;
    float* cs   = ivs + 128;
    float* b1s  = cs + 128;
    float* b2s  = b1s + 128;

    const int tid = threadIdx.x;
    const int wid = tid >> 5, lid = tid & 31;
    const int g = lid >> 2, tg = lid & 3;
    const long long pbase = (long long)blockIdx.x * TM;

    // ---- constants ----
    if (tid < 128) {
        float v  = fabsf(gstds[tid]) + 0.01f;
        float iv = 1.0f / v;
        mus[tid] = gmeans[tid];
        ivs[tid] = iv;
        cs[tid]  = -0.3989422804014327f * iv;
        b1s[tid] = b1[tid];
    }
    if (tid < 32) b2s[tid] = b2[tid];

    // ---- stage W1 (128x128) / W2 (32x128) as fp16, plain K-major ----
    #pragma unroll
    for (int i = 0; i < 8; i++) {
        int v = tid + i * NT;                 // 128 rows x 32 float4
        int j = v >> 5, k4 = (v & 31) * 4;
        float4 w = *(const float4*)(W1 + j * KDIM + k4);
        int o = j * LD2 + (k4 >> 1);
        W1s[o + 0] = pack_h2(w.x, w.y);
        W1s[o + 1] = pack_h2(w.z, w.w);
    }
    #pragma unroll
    for (int i = 0; i < 2; i++) {
        int v = tid + i * NT;                 // 32 rows x 32 float4
        int j = v >> 5, k4 = (v & 31) * 4;
        float4 w = *(const float4*)(W2 + j * KDIM + k4);
        int o = j * LD2 + (k4 >> 1);
        W2s[o + 0] = pack_h2(w.x, w.y);
        W2s[o + 1] = pack_h2(w.z, w.w);
    }

    // ---- per-pair scalar s ----
    if (tid < TM) {
        long long p = pbase + tid;
        float sval = 0.0f;
        if (p < Ptotal) {
            int gg = (int)(p / nn);
            long long r = p - (long long)gg * nn;
            int i = (int)(r / n);
            int j = (int)(r - (long long)i * n);
            int gi = gg * n + i, gj = gg * n + j;
            float dx = coord[gi * 3 + 0] - coord[gj * 3 + 0];
            float dy = coord[gi * 3 + 1] - coord[gj * 3 + 1];
            float dz = coord[gi * 3 + 2] - coord[gj * 3 + 2];
            float d2 = dx * dx + dy * dy + dz * dz;
            float dist = (d2 > 0.0f) ? sqrtf(d2) : 0.0f;
            int ti = node_type[gi], tj = node_type[gj];
            float mul = mul_w[ti * 2 + 0] + mul_w[tj * 2 + 1];
            float bia = bias_w[ti * 2 + 0] + bias_w[tj * 2 + 1];
            sval = mul * dist + bia;
        }
        s_sm[tid] = sval;
    }
    __syncthreads();

    // ---- G[m][k] = exp(-0.5*((s-mu)*iv)^2)*c  -> fp16 pairs ----
    #pragma unroll 4
    for (int i = 0; i < 16; i++) {
        int idx = tid + i * NT;              // 128 rows x 64 half2-words
        int m = idx >> 6, kw = idx & 63;
        int k = kw * 2;
        float s = s_sm[m];
        float2 mu = *(float2*)(mus + k);
        float2 iv = *(float2*)(ivs + k);
        float2 cc = *(float2*)(cs + k);
        float t0 = (s - mu.x) * iv.x;
        float t1 = (s - mu.y) * iv.y;
        Gs[m * LD2 + kw] = pack_h2(__expf(-0.5f * t0 * t0) * cc.x,
                                   __expf(-0.5f * t1 * t1) * cc.y);
    }
    __syncthreads();

    // ---- GEMM1: D[128x128] = G @ W1^T, 4x4 warp grid, 32x32 tiles ----
    const int wm = wid >> 2, wn = wid & 3;
    const int ra = wm * 32 + g;
    const int bn = wn * 32;

    float acc[2][4][4];
    #pragma unroll
    for (int mt = 0; mt < 2; mt++)
        #pragma unroll
        for (int nt = 0; nt < 4; nt++)
            #pragma unroll
            for (int q = 0; q < 4; q++) acc[mt][nt][q] = 0.0f;

    {
        const uint32_t* Arow = Gs + ra * LD2 + tg;
        const uint32_t* Brow = W1s + (bn + g) * LD2 + tg;
        #pragma unroll
        for (int s = 0; s < 8; s++) {          // k16 steps
            const int kb = s * 8;
            uint32_t a[2][4], b[4][2];
            #pragma unroll
            for (int mt = 0; mt < 2; mt++) {
                a[mt][0] = Arow[(mt * 16) * LD2 + kb];
                a[mt][1] = Arow[(mt * 16 + 8) * LD2 + kb];
                a[mt][2] = Arow[(mt * 16) * LD2 + kb + 4];
                a[mt][3] = Arow[(mt * 16 + 8) * LD2 + kb + 4];
            }
            #pragma unroll
            for (int nt = 0; nt < 4; nt++) {
                b[nt][0] = Brow[(nt * 8) * LD2 + kb];
                b[nt][1] = Brow[(nt * 8) * LD2 + kb + 4];
            }
            #pragma unroll
            for (int mt = 0; mt < 2; mt++)
                #pragma unroll
                for (int nt = 0; nt < 4; nt++)
                    mma16(acc[mt][nt][0], acc[mt][nt][1], acc[mt][nt][2], acc[mt][nt][3],
                          a[mt][0], a[mt][1], a[mt][2], a[mt][3],
                          b[nt][0], b[nt][1]);
        }
    }
    __syncthreads();   // all warps done reading G

    // ---- bias + exact GELU -> h (fp16) back into G buffer ----
    #pragma unroll
    for (int mt = 0; mt < 2; mt++) {
        int r0 = ra + mt * 16;
        #pragma unroll
        for (int nt = 0; nt < 4; nt++) {
            int col = bn + nt * 8 + 2 * tg;             // half index (even)
            float bb0 = b1s[col], bb1 = b1s[col + 1];
            int wo = (col >> 1);                        // word index
            Gs[r0 * LD2 + wo] =
                pack_h2(gelu_exact(acc[mt][nt][0] + bb0),
                        gelu_exact(acc[mt][nt][1] + bb1));
            Gs[(r0 + 8) * LD2 + wo] =
                pack_h2(gelu_exact(acc[mt][nt][2] + bb0),
                        gelu_exact(acc[mt][nt][3] + bb1));
        }
    }
    __syncthreads();

    // ---- GEMM2: out[128x32] = h @ W2^T; warp = (m-tile, n-half) ----
    {
        const int mt2 = wid >> 1, nh = wid & 1;
        const int ra2 = mt2 * 16 + g;

        float acc2[2][4];
        #pragma unroll
        for (int nt = 0; nt < 2; nt++)
            #pragma unroll
            for (int q = 0; q < 4; q++) acc2[nt][q] = 0.0f;

        const uint32_t* Arow = Gs + ra2 * LD2 + tg;
        const uint32_t* Brow = W2s + (nh * 16 + g) * LD2 + tg;
        #pragma unroll
        for (int s = 0; s < 8; s++) {
            const int kb = s * 8;
            uint32_t a0 = Arow[kb];
            uint32_t a1 = Arow[8 * LD2 + kb];
            uint32_t a2 = Arow[kb + 4];
            uint32_t a3 = Arow[8 * LD2 + kb + 4];
            #pragma unroll
            for (int nt = 0; nt < 2; nt++) {
                uint32_t b0 = Brow[(nt * 8) * LD2 + kb];
                uint32_t b1v = Brow[(nt * 8) * LD2 + kb + 4];
                mma16(acc2[nt][0], acc2[nt][1], acc2[nt][2], acc2[nt][3],
                      a0, a1, a2, a3, b0, b1v);
            }
        }

        long long p0 = pbase + mt2 * 16 + g;
        long long p1 = p0 + 8;
        #pragma unroll
        for (int nt = 0; nt < 2; nt++) {
            int col = nh * 16 + nt * 8 + 2 * tg;
            float bb0 = b2s[col], bb1 = b2s[col + 1];
            if (p0 < Ptotal)
                *(float2*)(out + p0 * HDIM + col) =
                    make_float2(acc2[nt][0] + bb0, acc2[nt][1] + bb1);
            if (p1 < Ptotal)
                *(float2*)(out + p1 * HDIM + col) =
                    make_float2(acc2[nt][2] + bb0, acc2[nt][3] + bb1);
        }
    }
}

extern "C" void kernel_launch(void* const* d_in, const int* in_sizes, int n_in,
                              void* d_out, int out_size) {
    const float* coord     = (const float*)d_in[0];
    const int*   node_type = (const int*)  d_in[1];
    const float* gmeans    = (const float*)d_in[2];
    const float* gstds     = (const float*)d_in[3];
    const float* mul_w     = (const float*)d_in[4];
    const float* bias_w    = (const float*)d_in[5];
    const float* W1        = (const float*)d_in[6];
    const float* b1        = (const float*)d_in[7];
    const float* W2        = (const float*)d_in[8];
    const float* b2        = (const float*)d_in[9];
    float* out = (float*)d_out;

    const int Kk = in_sizes[7];
    const int Hh = in_sizes[9];
    if (Kk != KDIM || Hh != HDIM) return;
    const long long BN = in_sizes[1];
    const long long n  = (long long)out_size / (BN * Hh);
    const long long nn = n * n;
    const long long B  = BN / n;
    const long long P  = B * nn;

    const int nblocks = (int)((P + TM - 1) / TM);

    cudaFuncSetAttribute(spatial_encoder_h16,
                         cudaFuncAttributeMaxDynamicSharedMemorySize,
                         (int)SMEM_BYTES);

    spatial_encoder_h16<<<nblocks, NT, SMEM_BYTES>>>(
        coord, node_type, gmeans, gstds, mul_w, bias_w,
        W1, b1, W2, b2, out, (int)n, nn, P);
}

// round 14
// speedup vs baseline: 1.0008x; 1.0008x over previous
#include <cuda_runtime.h>
#include <cuda_fp16.h>
#include <math.h>
#include <stdint.h>

#define KDIM 128
#define HDIM 32
#define TM   128
#define NT   512
#define LD2  68      // row stride in 32-bit words (=136 halves); 68 % 32 == 4 -> conflict-free

// ---------- helpers ----------
__device__ __forceinline__ uint32_t pack_h2(float a, float b) {
    __half2 h = __floats2half2_rn(a, b);
    return *reinterpret_cast<uint32_t*>(&h);
}
// D += A(16x16,row) * B(16x8,col)   fp16 -> f32
__device__ __forceinline__ void mma16(float& d0, float& d1, float& d2, float& d3,
                                      uint32_t a0, uint32_t a1, uint32_t a2, uint32_t a3,
                                      uint32_t b0, uint32_t b1) {
    asm("mma.sync.aligned.m16n8k16.row.col.f32.f16.f16.f32 "
        "{%0,%1,%2,%3}, {%4,%5,%6,%7}, {%8,%9}, {%0,%1,%2,%3};"
        : "+f"(d0), "+f"(d1), "+f"(d2), "+f"(d3)
        : "r"(a0), "r"(a1), "r"(a2), "r"(a3), "r"(b0), "r"(b1));
}
__device__ __forceinline__ float gelu_exact(float x) {
    return 0.5f * x * (1.0f + erff(x * 0.7071067811865476f));
}

// ---- smem word(32-bit) offsets ----
#define G_OFF   0u                        // 128*LD2 words (G, reused as h)
#define W1_OFF  (128u * LD2)              // 8704
#define W2_OFF  (W1_OFF + 128u * LD2)     // 17408
#define AUX_OFF (W2_OFF + 32u * LD2)      // 19584
// aux: s[128], mus[128], ivs[128], cs[128], b1s[128], b2s[32] = 672 floats
#define SMEM_BYTES ((AUX_OFF + 672u) * 4u)   // 81024 B -> 2 CTAs/SM

extern __shared__ float smem_f[];

__global__ __launch_bounds__(NT, 2)
void spatial_encoder_h16(
    const float* __restrict__ coord, const int* __restrict__ node_type,
    const float* __restrict__ gmeans, const float* __restrict__ gstds,
    const float* __restrict__ mul_w, const float* __restrict__ bias_w,
    const float* __restrict__ W1, const float* __restrict__ b1,
    const float* __restrict__ W2, const float* __restrict__ b2,
    float* __restrict__ out, int n, long long nn, long long Ptotal)
{
    uint32_t* Gs  = (uint32_t*)(smem_f + G_OFF);
    uint32_t* W1s = (uint32_t*)(smem_f + W1_OFF);
    uint32_t* W2s = (uint32_t*)(smem_f + W2_OFF);
    float* s_sm = smem_f + AUX_OFF;
    float* mus  = s_sm + 128;
    float* ivs  = mus + 128;
    float* cs   = ivs + 128;
    float* b1s  = cs + 128;
    float* b2s  = b1s + 128;

    const int tid = threadIdx.x;
    const int wid = tid >> 5, lid = tid & 31;
    const int g = lid >> 2, tg = lid & 3;
    const long long pbase = (long long)blockIdx.x * TM;

    // ---- constants ----
    if (tid < 128) {
        float v  = fabsf(gstds[tid]) + 0.01f;
        float iv = 1.0f / v;
        mus[tid] = gmeans[tid];
        ivs[tid] = iv;
        cs[tid]  = -0.3989422804014327f * iv;
        b1s[tid] = b1[tid];
    }
    if (tid < 32) b2s[tid] = b2[tid];

    // ---- stage W1 (128x128) / W2 (32x128) as fp16, plain K-major ----
    #pragma unroll
    for (int i = 0; i < 8; i++) {
        int v = tid + i * NT;                 // 128 rows x 32 float4
        int j = v >> 5, k4 = (v & 31) * 4;
        float4 w = *(const float4*)(W1 + j * KDIM + k4);
        int o = j * LD2 + (k4 >> 1);
        W1s[o + 0] = pack_h2(w.x, w.y);
        W1s[o + 1] = pack_h2(w.z, w.w);
    }
    #pragma unroll
    for (int i = 0; i < 2; i++) {
        int v = tid + i * NT;                 // 32 rows x 32 float4
        int j = v >> 5, k4 = (v & 31) * 4;
        float4 w = *(const float4*)(W2 + j * KDIM + k4);
        int o = j * LD2 + (k4 >> 1);
        W2s[o + 0] = pack_h2(w.x, w.y);
        W2s[o + 1] = pack_h2(w.z, w.w);
    }

    // ---- per-pair scalar s ----
    if (tid < TM) {
        long long p = pbase + tid;
        float sval = 0.0f;
        if (p < Ptotal) {
            int gg = (int)(p / nn);
            long long r = p - (long long)gg * nn;
            int i = (int)(r / n);
            int j = (int)(r - (long long)i * n);
            int gi = gg * n + i, gj = gg * n + j;
            float dx = coord[gi * 3 + 0] - coord[gj * 3 + 0];
            float dy = coord[gi * 3 + 1] - coord[gj * 3 + 1];
            float dz = coord[gi * 3 + 2] - coord[gj * 3 + 2];
            float d2 = dx * dx + dy * dy + dz * dz;
            float dist = (d2 > 0.0f) ? sqrtf(d2) : 0.0f;
            int ti = node_type[gi], tj = node_type[gj];
            float mul = mul_w[ti * 2 + 0] + mul_w[tj * 2 + 1];
            float bia = bias_w[ti * 2 + 0] + bias_w[tj * 2 + 1];
            sval = mul * dist + bia;
        }
        s_sm[tid] = sval;
    }
    __syncthreads();

    // ---- G[m][k] = exp(-0.5*((s-mu)*iv)^2)*c  -> fp16 pairs ----
    #pragma unroll 4
    for (int i = 0; i < 16; i++) {
        int idx = tid + i * NT;              // 128 rows x 64 half2-words
        int m = idx >> 6, kw = idx & 63;
        int k = kw * 2;
        float s = s_sm[m];
        float2 mu = *(float2*)(mus + k);
        float2 iv = *(float2*)(ivs + k);
        float2 cc = *(float2*)(cs + k);
        float t0 = (s - mu.x) * iv.x;
        float t1 = (s - mu.y) * iv.y;
        Gs[m * LD2 + kw] = pack_h2(__expf(-0.5f * t0 * t0) * cc.x,
                                   __expf(-0.5f * t1 * t1) * cc.y);
    }
    __syncthreads();

    // ---- GEMM1: D[128x128] = G @ W1^T, 4x4 warp grid, 32x32 tiles ----
    const int wm = wid >> 2, wn = wid & 3;
    const int ra = wm * 32 + g;
    const int bn = wn * 32;

    float acc[2][4][4];
    #pragma unroll
    for (int mt = 0; mt < 2; mt++)
        #pragma unroll
        for (int nt = 0; nt < 4; nt++)
            #pragma unroll
            for (int q = 0; q < 4; q++) acc[mt][nt][q] = 0.0f;

    {
        const uint32_t* Arow = Gs + ra * LD2 + tg;
        const uint32_t* Brow = W1s + (bn + g) * LD2 + tg;
        #pragma unroll
        for (int s = 0; s < 8; s++) {          // k16 steps
            const int kb = s * 8;
            uint32_t a[2][4], b[4][2];
            #pragma unroll
            for (int mt = 0; mt < 2; mt++) {
                a[mt][0] = Arow[(mt * 16) * LD2 + kb];
                a[mt][1] = Arow[(mt * 16 + 8) * LD2 + kb];
                a[mt][2] = Arow[(mt * 16) * LD2 + kb + 4];
                a[mt][3] = Arow[(mt * 16 + 8) * LD2 + kb + 4];
            }
            #pragma unroll
            for (int nt = 0; nt < 4; nt++) {
                b[nt][0] = Brow[(nt * 8) * LD2 + kb];
                b[nt][1] = Brow[(nt * 8) * LD2 + kb + 4];
            }
            #pragma unroll
            for (int mt = 0; mt < 2; mt++)
                #pragma unroll
                for (int nt = 0; nt < 4; nt++)
                    mma16(acc[mt][nt][0], acc[mt][nt][1], acc[mt][nt][2], acc[mt][nt][3],
                          a[mt][0], a[mt][1], a[mt][2], a[mt][3],
                          b[nt][0], b[nt][1]);
        }
    }
    __syncthreads();   // all warps done reading G

    // ---- bias + exact GELU -> h (fp16) back into G buffer ----
    #pragma unroll
    for (int mt = 0; mt < 2; mt++) {
        int r0 = ra + mt * 16;
        #pragma unroll
        for (int nt = 0; nt < 4; nt++) {
            int col = bn + nt * 8 + 2 * tg;             // half index (even)
            float bb0 = b1s[col], bb1 = b1s[col + 1];
            int wo = (col >> 1);                        // word index
            Gs[r0 * LD2 + wo] =
                pack_h2(gelu_exact(acc[mt][nt][0] + bb0),
                        gelu_exact(acc[mt][nt][1] + bb1));
            Gs[(r0 + 8) * LD2 + wo] =
                pack_h2(gelu_exact(acc[mt][nt][2] + bb0),
                        gelu_exact(acc[mt][nt][3] + bb1));
        }
    }
    __syncthreads();

    // ---- GEMM2: out[128x32] = h @ W2^T; warp = (m-tile, n-half) ----
    {
        const int mt2 = wid >> 1, nh = wid & 1;
        const int ra2 = mt2 * 16 + g;

        float acc2[2][4];
        #pragma unroll
        for (int nt = 0; nt < 2; nt++)
            #pragma unroll
            for (int q = 0; q < 4; q++) acc2[nt][q] = 0.0f;

        const uint32_t* Arow = Gs + ra2 * LD2 + tg;
        const uint32_t* Brow = W2s + (nh * 16 + g) * LD2 + tg;
        #pragma unroll
        for (int s = 0; s < 8; s++) {
            const int kb = s * 8;
            uint32_t a0 = Arow[kb];
            uint32_t a1 = Arow[8 * LD2 + kb];
            uint32_t a2 = Arow[kb + 4];
            uint32_t a3 = Arow[8 * LD2 + kb + 4];
            #pragma unroll
            for (int nt = 0; nt < 2; nt++) {
                uint32_t b0 = Brow[(nt * 8) * LD2 + kb];
                uint32_t b1v = Brow[(nt * 8) * LD2 + kb + 4];
                mma16(acc2[nt][0], acc2[nt][1], acc2[nt][2], acc2[nt][3],
                      a0, a1, a2, a3, b0, b1v);
            }
        }

        long long p0 = pbase + mt2 * 16 + g;
        long long p1 = p0 + 8;
        #pragma unroll
        for (int nt = 0; nt < 2; nt++) {
            int col = nh * 16 + nt * 8 + 2 * tg;
            float bb0 = b2s[col], bb1 = b2s[col + 1];
            if (p0 < Ptotal)
                *(float2*)(out + p0 * HDIM + col) =
                    make_float2(acc2[nt][0] + bb0, acc2[nt][1] + bb1);
            if (p1 < Ptotal)
                *(float2*)(out + p1 * HDIM + col) =
                    make_float2(acc2[nt][2] + bb0, acc2[nt][3] + bb1);
        }
    }
}

extern "C" void kernel_launch(void* const* d_in, const int* in_sizes, int n_in,
                              void* d_out, int out_size) {
    const float* coord     = (const float*)d_in[0];
    const int*   node_type = (const int*)  d_in[1];
    const float* gmeans    = (const float*)d_in[2];
    const float* gstds     = (const float*)d_in[3];
    const float* mul_w     = (const float*)d_in[4];
    const float* bias_w    = (const float*)d_in[5];
    const float* W1        = (const float*)d_in[6];
    const float* b1        = (const float*)d_in[7];
    const float* W2        = (const float*)d_in[8];
    const float* b2        = (const float*)d_in[9];
    float* out = (float*)d_out;

    const int Kk = in_sizes[7];
    const int Hh = in_sizes[9];
    if (Kk != KDIM || Hh != HDIM) return;
    const long long BN = in_sizes[1];
    const long long n  = (long long)out_size / (BN * Hh);
    const long long nn = n * n;
    const long long B  = BN / n;
    const long long P  = B * nn;

    const int nblocks = (int)((P + TM - 1) / TM);

    cudaFuncSetAttribute(spatial_encoder_h16,
                         cudaFuncAttributeMaxDynamicSharedMemorySize,
                         (int)SMEM_BYTES);

    spatial_encoder_h16<<<nblocks, NT, SMEM_BYTES>>>(
        coord, node_type, gmeans, gstds, mul_w, bias_w,
        W1, b1, W2, b2, out, (int)n, nn, P);
}